// round 6
// baseline (speedup 1.0000x reference)
#include <cuda_runtime.h>
#include <math.h>

#define NN 20000
#define EE 640000

// ---------------- scratch (static device globals; no allocation) ----------------
__device__ float g_q[NN * 128];
__device__ float g_k[NN * 128];
__device__ float g_v[NN * 128];
__device__ float g_vpsi[NN * 128];
__device__ float g_hcat[NN * 256];
__device__ int   g_row[EE];
__device__ int   g_col[EE];
__device__ int   g_scol[EE];
__device__ int   g_counts[NN];
__device__ int   g_off[NN + 1];
__device__ int   g_cur[NN];
__device__ int   g_is64;

// ---------------- edge_index dtype detection (int64 vs int32) ----------------
// If data is int64 (values < 20000), every odd 32-bit word of the first 32
// entries is 0. For genuine int32 data the probability of that is ~(1/2e4)^32.
__global__ void detect_kernel(const int* __restrict__ p) {
    int l = threadIdx.x;
    int bad = (p[2 * l + 1] != 0);
    unsigned m = __ballot_sync(0xffffffffu, bad);
    if (l == 0) g_is64 = (m == 0u) ? 1 : 0;
}

__global__ void decode_kernel(const void* __restrict__ ei) {
    int e = blockIdx.x * 1024 + threadIdx.x;
    if (g_is64) {
        const long long* q = (const long long*)ei;
        g_row[e] = (int)q[e];
        g_col[e] = (int)q[EE + e];
    } else {
        const int* q = (const int*)ei;
        g_row[e] = q[e];
        g_col[e] = q[EE + e];
    }
}

// ---------------- counting sort of edges by destination row ----------------
__global__ void zero_kernel() {
    int i = blockIdx.x * 1024 + threadIdx.x;
    if (i < NN) g_counts[i] = 0;
}

__global__ void hist_kernel() {
    int e = blockIdx.x * 1024 + threadIdx.x;
    atomicAdd(&g_counts[g_row[e]], 1);
}

__global__ void scan_kernel() {
    __shared__ int part[1024];
    const int t = threadIdx.x;
    const int CH = 20;                     // 1024*20 = 20480 >= NN
    int base = t * CH;
    int loc[20];
    int s = 0;
#pragma unroll
    for (int i = 0; i < CH; i++) {
        int idx = base + i;
        int cv = (idx < NN) ? g_counts[idx] : 0;
        loc[i] = s;
        s += cv;
    }
    part[t] = s;
    __syncthreads();
    for (int off = 1; off < 1024; off <<= 1) {
        int v = (t >= off) ? part[t - off] : 0;
        __syncthreads();
        part[t] += v;
        __syncthreads();
    }
    int basesum = part[t] - s;             // exclusive prefix of this chunk
#pragma unroll
    for (int i = 0; i < CH; i++) {
        int idx = base + i;
        if (idx < NN) {
            int o = basesum + loc[i];
            g_off[idx] = o;
            g_cur[idx] = o;
        }
    }
    if (t == 1023) g_off[NN] = part[1023]; // == EE
}

__global__ void scatter_kernel() {
    int e = blockIdx.x * 1024 + threadIdx.x;
    int r = g_row[e];
    int p = atomicAdd(&g_cur[r], 1);
    g_scol[p] = g_col[e];
}

// ---------------- node GEMM: C[N,128] = X[N,128] @ W[128,128] + b ----------------
// 64 rows/block, full W in smem, bank-conflict-free: thread (rl=t>>2, g=t&3)
// owns cols {4g + 16*jj + e}.
__global__ void __launch_bounds__(256) gemm_node(const float* __restrict__ X,
                                                 const float* __restrict__ W,
                                                 const float* __restrict__ B,
                                                 int which) {
    extern __shared__ float sm[];
    float* Xs = sm;              // 64 x 132 (padded)
    float* Ws = sm + 64 * 132;   // 128 x 128
    float* C = (which == 0) ? g_q : (which == 1) ? g_k : g_v;

    const int t = threadIdx.x;
    const int r0 = blockIdx.x * 64;

    for (int i = t; i < 64 * 32; i += 256) {          // X tile as float4
        int row = i >> 5, c4 = i & 31;
        int gr = r0 + row;
        float4 val = make_float4(0.f, 0.f, 0.f, 0.f);
        if (gr < NN) val = ((const float4*)(X + (long)gr * 128))[c4];
        *((float4*)(Xs + row * 132) + c4) = val;
    }
    for (int i = t; i < 128 * 32; i += 256)
        ((float4*)Ws)[i] = ((const float4*)W)[i];
    __syncthreads();

    const int rl = t >> 2;
    const int g = t & 3;
    float acc[32];
#pragma unroll
    for (int jj = 0; jj < 8; jj++) {
        float4 bv = *((const float4*)(B + g * 4 + 16 * jj));
        acc[jj * 4 + 0] = bv.x; acc[jj * 4 + 1] = bv.y;
        acc[jj * 4 + 2] = bv.z; acc[jj * 4 + 3] = bv.w;
    }
    const float* xrow = Xs + rl * 132;
#pragma unroll 4
    for (int k = 0; k < 128; k++) {
        float xv = xrow[k];
        const float* wr = Ws + k * 128 + g * 4;
#pragma unroll
        for (int jj = 0; jj < 8; jj++) {
            float4 wv = *((const float4*)(wr + 16 * jj));
            acc[jj * 4 + 0] = fmaf(xv, wv.x, acc[jj * 4 + 0]);
            acc[jj * 4 + 1] = fmaf(xv, wv.y, acc[jj * 4 + 1]);
            acc[jj * 4 + 2] = fmaf(xv, wv.z, acc[jj * 4 + 2]);
            acc[jj * 4 + 3] = fmaf(xv, wv.w, acc[jj * 4 + 3]);
        }
    }
    int gr = r0 + rl;
    if (gr < NN) {
#pragma unroll
        for (int jj = 0; jj < 8; jj++) {
            float4 o = make_float4(acc[jj * 4 + 0], acc[jj * 4 + 1],
                                   acc[jj * 4 + 2], acc[jj * 4 + 3]);
            *((float4*)(C + (long)gr * 128 + g * 4 + 16 * jj)) = o;
        }
    }
}

// ---------------- vpsi[n,h,:] = tanh(v[n,h,:] @ Wpsi + bpsi) ----------------
__global__ void __launch_bounds__(256) vpsi_kernel(const float* __restrict__ Wpsi,
                                                   const float* __restrict__ bpsi) {
    __shared__ float Wp[256];
    __shared__ float vs[256];
    int t = threadIdx.x;
    Wp[t] = Wpsi[t];
    int r = blockIdx.x * 2 + (t >> 7);
    int c = t & 127;
    vs[t] = g_v[(long)r * 128 + c];
    __syncthreads();
    int head = c >> 4, dout = c & 15;
    float s = bpsi[dout];
    const float* vh = vs + (t & 128) + head * 16;
#pragma unroll
    for (int d = 0; d < 16; d++) s = fmaf(vh[d], Wp[d * 16 + dout], s);
    g_vpsi[(long)r * 128 + c] = tanhf(s);
}

// ---------------- fused edge pass: one warp per destination row ----------------
// lane holds dims 4l..4l+3 (head = l/4). Per edge: dot(q,k) via 4-lane
// butterfly, w = exp(l/sqrt(D)), accumulate w*v and w*vpsi, normalize by the
// head sum at the end (softmax denominator). 2-way unroll for MLP.
__global__ void __launch_bounds__(256) edge_kernel() {
    const int r = (blockIdx.x << 3) + (threadIdx.x >> 5);
    const int lane = threadIdx.x & 31;
    const int s0 = g_off[r];
    const int s1 = g_off[r + 1];
    const float4 qv = *((const float4*)(g_q + (long)r * 128) + lane);
    float4 alp = make_float4(0.f, 0.f, 0.f, 0.f);
    float4 abp = make_float4(0.f, 0.f, 0.f, 0.f);
    float ssum = 0.f;
    int e = s0;
    for (; e + 2 <= s1; e += 2) {
        const int c0 = g_scol[e];
        const int c1 = g_scol[e + 1];
        const float4 k0 = *((const float4*)(g_k + (long)c0 * 128) + lane);
        const float4 k1 = *((const float4*)(g_k + (long)c1 * 128) + lane);
        const float4 v0 = *((const float4*)(g_v + (long)c0 * 128) + lane);
        const float4 v1 = *((const float4*)(g_v + (long)c1 * 128) + lane);
        const float4 p0 = *((const float4*)(g_vpsi + (long)c0 * 128) + lane);
        const float4 p1 = *((const float4*)(g_vpsi + (long)c1 * 128) + lane);
        float d0 = fmaf(qv.x, k0.x, fmaf(qv.y, k0.y, fmaf(qv.z, k0.z, qv.w * k0.w)));
        float d1 = fmaf(qv.x, k1.x, fmaf(qv.y, k1.y, fmaf(qv.z, k1.z, qv.w * k1.w)));
        d0 += __shfl_xor_sync(0xffffffffu, d0, 1);
        d1 += __shfl_xor_sync(0xffffffffu, d1, 1);
        d0 += __shfl_xor_sync(0xffffffffu, d0, 2);
        d1 += __shfl_xor_sync(0xffffffffu, d1, 2);
        const float w0 = __expf(d0 * 0.25f);
        const float w1 = __expf(d1 * 0.25f);
        ssum += w0 + w1;
        alp.x = fmaf(w0, v0.x, alp.x); alp.y = fmaf(w0, v0.y, alp.y);
        alp.z = fmaf(w0, v0.z, alp.z); alp.w = fmaf(w0, v0.w, alp.w);
        alp.x = fmaf(w1, v1.x, alp.x); alp.y = fmaf(w1, v1.y, alp.y);
        alp.z = fmaf(w1, v1.z, alp.z); alp.w = fmaf(w1, v1.w, alp.w);
        abp.x = fmaf(w0, p0.x, abp.x); abp.y = fmaf(w0, p0.y, abp.y);
        abp.z = fmaf(w0, p0.z, abp.z); abp.w = fmaf(w0, p0.w, abp.w);
        abp.x = fmaf(w1, p1.x, abp.x); abp.y = fmaf(w1, p1.y, abp.y);
        abp.z = fmaf(w1, p1.z, abp.z); abp.w = fmaf(w1, p1.w, abp.w);
    }
    if (e < s1) {
        const int c0 = g_scol[e];
        const float4 k0 = *((const float4*)(g_k + (long)c0 * 128) + lane);
        const float4 v0 = *((const float4*)(g_v + (long)c0 * 128) + lane);
        const float4 p0 = *((const float4*)(g_vpsi + (long)c0 * 128) + lane);
        float d0 = fmaf(qv.x, k0.x, fmaf(qv.y, k0.y, fmaf(qv.z, k0.z, qv.w * k0.w)));
        d0 += __shfl_xor_sync(0xffffffffu, d0, 1);
        d0 += __shfl_xor_sync(0xffffffffu, d0, 2);
        const float w0 = __expf(d0 * 0.25f);
        ssum += w0;
        alp.x = fmaf(w0, v0.x, alp.x); alp.y = fmaf(w0, v0.y, alp.y);
        alp.z = fmaf(w0, v0.z, alp.z); alp.w = fmaf(w0, v0.w, alp.w);
        abp.x = fmaf(w0, p0.x, abp.x); abp.y = fmaf(w0, p0.y, abp.y);
        abp.z = fmaf(w0, p0.z, abp.z); abp.w = fmaf(w0, p0.w, abp.w);
    }
    const float inv = 1.f / (ssum + 1e-16f);
    float4 o;
    o.x = alp.x * inv; o.y = alp.y * inv; o.z = alp.z * inv; o.w = alp.w * inv;
    *((float4*)(g_hcat + (long)r * 256) + lane) = o;
    o.x = abp.x * inv; o.y = abp.y * inv; o.z = abp.z * inv; o.w = abp.w * inv;
    *((float4*)(g_hcat + (long)r * 256 + 128) + lane) = o;
}

// ---------------- output GEMM + residual + ReLU + LayerNorm ----------------
// 32 rows/block; full Wo[256,128] in smem; thread (rl=t>>3, g=t&7) owns cols
// {4g + 32*jj + e} -> conflict-free smem phases and coalesced stores.
__global__ void __launch_bounds__(256) final_kernel(const float* __restrict__ X,
                                                    const float* __restrict__ Wo,
                                                    const float* __restrict__ bo,
                                                    const float* __restrict__ gamma,
                                                    const float* __restrict__ beta,
                                                    float* __restrict__ Y) {
    extern __shared__ float sm[];
    float* Ws = sm;                       // 256 x 128
    float* Hs = sm + 256 * 128;           // 32 x 260 (padded)
    float* redS = Hs + 32 * 260;          // 32 x 8
    float* redQ = redS + 256;             // 32 x 8

    const int t = threadIdx.x;
    const int r0 = blockIdx.x * 32;

    for (int i = t; i < 256 * 32; i += 256)
        ((float4*)Ws)[i] = ((const float4*)Wo)[i];
    for (int i = t; i < 32 * 64; i += 256) {
        int row = i >> 6, c4 = i & 63;
        *((float4*)(Hs + row * 260) + c4) =
            ((const float4*)(g_hcat + (long)(r0 + row) * 256))[c4];
    }
    __syncthreads();

    const int rl = t >> 3;
    const int g = t & 7;
    const int grow = r0 + rl;

    float acc[16];
#pragma unroll
    for (int jj = 0; jj < 4; jj++) {
        float4 bv = *((const float4*)(bo + g * 4 + 32 * jj));
        acc[jj * 4 + 0] = bv.x; acc[jj * 4 + 1] = bv.y;
        acc[jj * 4 + 2] = bv.z; acc[jj * 4 + 3] = bv.w;
    }
    const float* hrow = Hs + rl * 260;
#pragma unroll 2
    for (int k = 0; k < 256; k++) {
        float xv = hrow[k];
        const float* wr = Ws + k * 128 + g * 4;
#pragma unroll
        for (int jj = 0; jj < 4; jj++) {
            float4 wv = *((const float4*)(wr + 32 * jj));
            acc[jj * 4 + 0] = fmaf(xv, wv.x, acc[jj * 4 + 0]);
            acc[jj * 4 + 1] = fmaf(xv, wv.y, acc[jj * 4 + 1]);
            acc[jj * 4 + 2] = fmaf(xv, wv.z, acc[jj * 4 + 2]);
            acc[jj * 4 + 3] = fmaf(xv, wv.w, acc[jj * 4 + 3]);
        }
    }
    // y = x + relu(h_out); per-thread partial moments
    float psum = 0.f, psq = 0.f;
#pragma unroll
    for (int jj = 0; jj < 4; jj++) {
        float4 xv = *((const float4*)(X + (long)grow * 128 + g * 4 + 32 * jj));
        float y0 = xv.x + fmaxf(acc[jj * 4 + 0], 0.f);
        float y1 = xv.y + fmaxf(acc[jj * 4 + 1], 0.f);
        float y2 = xv.z + fmaxf(acc[jj * 4 + 2], 0.f);
        float y3 = xv.w + fmaxf(acc[jj * 4 + 3], 0.f);
        acc[jj * 4 + 0] = y0; acc[jj * 4 + 1] = y1;
        acc[jj * 4 + 2] = y2; acc[jj * 4 + 3] = y3;
        psum += y0 + y1 + y2 + y3;
        psq += y0 * y0 + y1 * y1 + y2 * y2 + y3 * y3;
    }
    redS[rl * 8 + g] = psum;
    redQ[rl * 8 + g] = psq;
    __syncthreads();
    float mu = 0.f, sq = 0.f;
#pragma unroll
    for (int i = 0; i < 8; i++) { mu += redS[rl * 8 + i]; sq += redQ[rl * 8 + i]; }
    mu *= (1.f / 128.f);
    sq *= (1.f / 128.f);
    const float rsig = rsqrtf(sq - mu * mu + 1e-5f);
#pragma unroll
    for (int jj = 0; jj < 4; jj++) {
        int cb = g * 4 + 32 * jj;
        float4 gm = *((const float4*)(gamma + cb));
        float4 bt = *((const float4*)(beta + cb));
        float4 o;
        o.x = (acc[jj * 4 + 0] - mu) * rsig * gm.x + bt.x;
        o.y = (acc[jj * 4 + 1] - mu) * rsig * gm.y + bt.y;
        o.z = (acc[jj * 4 + 2] - mu) * rsig * gm.z + bt.z;
        o.w = (acc[jj * 4 + 3] - mu) * rsig * gm.w + bt.w;
        *((float4*)(Y + (long)grow * 128 + cb)) = o;
    }
}

// ---------------- launch ----------------
extern "C" void kernel_launch(void* const* d_in, const int* in_sizes, int n_in,
                              void* d_out, int out_size) {
    const float* x     = (const float*)d_in[0];
    const void*  ei    = d_in[1];
    const float* Wq    = (const float*)d_in[2];
    const float* bq    = (const float*)d_in[3];
    const float* Wk    = (const float*)d_in[4];
    const float* bk    = (const float*)d_in[5];
    const float* Wv    = (const float*)d_in[6];
    const float* bv    = (const float*)d_in[7];
    const float* Wpsi  = (const float*)d_in[8];
    const float* bpsi  = (const float*)d_in[9];
    const float* Wo    = (const float*)d_in[10];
    const float* bo    = (const float*)d_in[11];
    const float* gamma = (const float*)d_in[12];
    const float* beta  = (const float*)d_in[13];
    float* out = (float*)d_out;
    (void)in_sizes; (void)n_in; (void)out_size;

    (void)cudaFuncSetAttribute(gemm_node, cudaFuncAttributeMaxDynamicSharedMemorySize, 99328);
    (void)cudaFuncSetAttribute(final_kernel, cudaFuncAttributeMaxDynamicSharedMemorySize, 166400);

    // edge preprocessing (counting sort by destination row)
    detect_kernel<<<1, 32>>>((const int*)ei);
    decode_kernel<<<EE / 1024, 1024>>>(ei);
    zero_kernel<<<(NN + 1023) / 1024, 1024>>>();
    hist_kernel<<<EE / 1024, 1024>>>();
    scan_kernel<<<1, 1024>>>();
    scatter_kernel<<<EE / 1024, 1024>>>();

    // node-level projections
    gemm_node<<<(NN + 63) / 64, 256, 99328>>>(x, Wq, bq, 0);
    gemm_node<<<(NN + 63) / 64, 256, 99328>>>(x, Wk, bk, 1);
    gemm_node<<<(NN + 63) / 64, 256, 99328>>>(x, Wv, bv, 2);
    vpsi_kernel<<<NN / 2, 256>>>(Wpsi, bpsi);

    // fused attention edge pass
    edge_kernel<<<NN / 8, 256>>>();

    // output projection + residual + ReLU + LayerNorm
    final_kernel<<<NN / 32, 256, 166400>>>(x, Wo, bo, gamma, beta, out);
}

// round 8
// speedup vs baseline: 1.6995x; 1.6995x over previous
#include <cuda_runtime.h>
#include <cuda_fp16.h>
#include <math.h>

#define NN 20000
#define EE 640000

// ---------------- scratch (static device globals; no allocation) ----------------
__device__ float  g_q[NN * 128];
__device__ float  g_v[NN * 128];          // fp32 v (input to psi)
__device__ __half g_kvp[NN * 384];        // packed per-node record: k[128] | v[128] | psi[128]
__device__ float  g_hcat[NN * 256];
__device__ int    g_row[EE];
__device__ int    g_col[EE];
__device__ int    g_scol[EE];
__device__ int    g_counts[NN];
__device__ int    g_off[NN + 1];
__device__ int    g_cur[NN];
__device__ int    g_is64;

// ---------------- edge_index dtype detection (int64 vs int32) ----------------
__global__ void detect_kernel(const int* __restrict__ p) {
    int l = threadIdx.x;
    int bad = (p[2 * l + 1] != 0);
    unsigned m = __ballot_sync(0xffffffffu, bad);
    if (l == 0) g_is64 = (m == 0u) ? 1 : 0;
}

// ---------------- fused decode + histogram ----------------
__global__ void decode_hist_kernel(const void* __restrict__ ei) {
    int e = blockIdx.x * 1024 + threadIdx.x;
    int r, c;
    if (g_is64) {
        const long long* q = (const long long*)ei;
        r = (int)q[e]; c = (int)q[EE + e];
    } else {
        const int* q = (const int*)ei;
        r = q[e]; c = q[EE + e];
    }
    g_row[e] = r;
    g_col[e] = c;
    atomicAdd(&g_counts[r], 1);
}

__global__ void zero_kernel() {
    int i = blockIdx.x * 1024 + threadIdx.x;
    if (i < NN) g_counts[i] = 0;
}

__global__ void scan_kernel() {
    __shared__ int part[1024];
    const int t = threadIdx.x;
    const int CH = 20;                     // 1024*20 = 20480 >= NN
    int base = t * CH;
    int loc[20];
    int s = 0;
#pragma unroll
    for (int i = 0; i < CH; i++) {
        int idx = base + i;
        int cv = (idx < NN) ? g_counts[idx] : 0;
        loc[i] = s;
        s += cv;
    }
    part[t] = s;
    __syncthreads();
    for (int off = 1; off < 1024; off <<= 1) {
        int v = (t >= off) ? part[t - off] : 0;
        __syncthreads();
        part[t] += v;
        __syncthreads();
    }
    int basesum = part[t] - s;
#pragma unroll
    for (int i = 0; i < CH; i++) {
        int idx = base + i;
        if (idx < NN) {
            int o = basesum + loc[i];
            g_off[idx] = o;
            g_cur[idx] = o;
        }
    }
    if (t == 1023) g_off[NN] = part[1023];
}

__global__ void scatter_kernel() {
    int e = blockIdx.x * 1024 + threadIdx.x;
    int r = g_row[e];
    int p = atomicAdd(&g_cur[r], 1);
    g_scol[p] = g_col[e];
}

// ---------------- fused QKV GEMM: register-tiled, FMA-bound ----------------
// Block: 64 rows x 128 cols, 256 threads, each thread 4 rows x 8 cols.
// X tile stored k-major (transposed) so a-frag is one LDS.128 (broadcast).
// Per k-step: 3 LDS.128 (48B) per 32 FMA -> under the 128B/cyc crossbar.
// grid.y selects (Wq,bq)->g_q fp32, (Wk,bk)->g_kvp halves, (Wv,bv)->g_v fp32.
__global__ void __launch_bounds__(256) gemm_qkv(const float* __restrict__ X,
                                                const float* __restrict__ Wq, const float* __restrict__ bq,
                                                const float* __restrict__ Wk, const float* __restrict__ bk,
                                                const float* __restrict__ Wv, const float* __restrict__ bv) {
    extern __shared__ float sm[];
    float* Xs = sm;              // [128 k][68] transposed X tile (rows 0..63)
    float* Ws = sm + 128 * 68;   // [128 k][128 col]

    const int t = threadIdx.x;
    const int r0 = blockIdx.x * 64;
    const int which = blockIdx.y;
    const float* W = (which == 0) ? Wq : (which == 1) ? Wk : Wv;
    const float* B = (which == 0) ? bq : (which == 1) ? bk : bv;

    for (int i = t; i < 64 * 32; i += 256) {
        int row = i >> 5, c4 = i & 31;
        int gr = r0 + row;
        float4 val = make_float4(0.f, 0.f, 0.f, 0.f);
        if (gr < NN) val = ((const float4*)(X + (size_t)gr * 128))[c4];
        Xs[(4 * c4 + 0) * 68 + row] = val.x;
        Xs[(4 * c4 + 1) * 68 + row] = val.y;
        Xs[(4 * c4 + 2) * 68 + row] = val.z;
        Xs[(4 * c4 + 3) * 68 + row] = val.w;
    }
    for (int i = t; i < 128 * 32; i += 256)
        ((float4*)Ws)[i] = ((const float4*)W)[i];
    __syncthreads();

    const int tx = t & 15;       // col group: cols tx*4..+3 and 64+tx*4..+3
    const int ty = t >> 4;       // row group: rows ty*4..+3

    float acc[4][8];
    {
        float4 c0 = *((const float4*)(B + tx * 4));
        float4 c1 = *((const float4*)(B + 64 + tx * 4));
#pragma unroll
        for (int i = 0; i < 4; i++) {
            acc[i][0] = c0.x; acc[i][1] = c0.y; acc[i][2] = c0.z; acc[i][3] = c0.w;
            acc[i][4] = c1.x; acc[i][5] = c1.y; acc[i][6] = c1.z; acc[i][7] = c1.w;
        }
    }

#pragma unroll 4
    for (int k = 0; k < 128; k++) {
        float4 a  = *((const float4*)(Xs + k * 68 + ty * 4));
        float4 b0 = *((const float4*)(Ws + k * 128 + tx * 4));
        float4 b1 = *((const float4*)(Ws + k * 128 + 64 + tx * 4));
        float av[4] = {a.x, a.y, a.z, a.w};
        float bw[8] = {b0.x, b0.y, b0.z, b0.w, b1.x, b1.y, b1.z, b1.w};
#pragma unroll
        for (int i = 0; i < 4; i++)
#pragma unroll
            for (int j = 0; j < 8; j++)
                acc[i][j] = fmaf(av[i], bw[j], acc[i][j]);
    }

#pragma unroll
    for (int i = 0; i < 4; i++) {
        int gr = r0 + ty * 4 + i;
        if (gr >= NN) continue;
        if (which == 1) {
            // K projection -> halves into packed record, offset 0
            __half* dst = g_kvp + (size_t)gr * 384;
            *((__half2*)(dst + tx * 4))     = __floats2half2_rn(acc[i][0], acc[i][1]);
            *((__half2*)(dst + tx * 4 + 2)) = __floats2half2_rn(acc[i][2], acc[i][3]);
            *((__half2*)(dst + 64 + tx * 4))     = __floats2half2_rn(acc[i][4], acc[i][5]);
            *((__half2*)(dst + 64 + tx * 4 + 2)) = __floats2half2_rn(acc[i][6], acc[i][7]);
        } else {
            float* C = (which == 0) ? g_q : g_v;
            *((float4*)(C + (size_t)gr * 128 + tx * 4)) =
                make_float4(acc[i][0], acc[i][1], acc[i][2], acc[i][3]);
            *((float4*)(C + (size_t)gr * 128 + 64 + tx * 4)) =
                make_float4(acc[i][4], acc[i][5], acc[i][6], acc[i][7]);
        }
    }
}

// ---------------- vpsi: psi = tanh(v @ Wpsi + bpsi); pack v and psi as halves ----------------
__global__ void __launch_bounds__(256) vpsi_kernel(const float* __restrict__ Wpsi,
                                                   const float* __restrict__ bpsi) {
    __shared__ float Wp[256];
    __shared__ float vs[256];
    int t = threadIdx.x;
    Wp[t] = Wpsi[t];
    int r = blockIdx.x * 2 + (t >> 7);
    int c = t & 127;
    float vval = g_v[(size_t)r * 128 + c];
    vs[t] = vval;
    __syncthreads();
    int head = c >> 4, dout = c & 15;
    float s = bpsi[dout];
    const float* vh = vs + (t & 128) + head * 16;
#pragma unroll
    for (int d = 0; d < 16; d++) s = fmaf(vh[d], Wp[d * 16 + dout], s);
    g_kvp[(size_t)r * 384 + 128 + c] = __float2half_rn(vval);
    g_kvp[(size_t)r * 384 + 256 + c] = __float2half_rn(tanhf(s));
}

// ---------------- fused edge pass: one warp per destination row ----------------
// Packed half record per source node: k|v|psi (768B). Per edge the warp loads
// 3x256B. fp32 math: dot via 4-lane butterfly, exp weight, fp32 accumulators,
// one normalization at the end (softmax denominator folds out of the max pass).
__global__ void __launch_bounds__(256) edge_kernel() {
    const int r = (blockIdx.x << 3) + (threadIdx.x >> 5);
    const int lane = threadIdx.x & 31;
    const int s0 = g_off[r];
    const int s1 = g_off[r + 1];
    const float4 qv = *((const float4*)(g_q + (size_t)r * 128) + lane);
    float4 alp = make_float4(0.f, 0.f, 0.f, 0.f);
    float4 abp = make_float4(0.f, 0.f, 0.f, 0.f);
    float ssum = 0.f;
    const uint2* kvp = (const uint2*)g_kvp;   // 96 uint2 (=384 halves) per node

    int e = s0;
    for (; e + 2 <= s1; e += 2) {
        const int c0 = g_scol[e];
        const int c1 = g_scol[e + 1];
        const uint2* b0 = kvp + c0 * 96 + lane;
        const uint2* b1 = kvp + c1 * 96 + lane;
        const uint2 k0 = b0[0],  k1 = b1[0];
        const uint2 v0 = b0[32], v1 = b1[32];
        const uint2 p0 = b0[64], p1 = b1[64];

        float2 k0a = __half22float2(*(const __half2*)&k0.x);
        float2 k0b = __half22float2(*(const __half2*)&k0.y);
        float2 k1a = __half22float2(*(const __half2*)&k1.x);
        float2 k1b = __half22float2(*(const __half2*)&k1.y);
        float d0 = fmaf(qv.x, k0a.x, fmaf(qv.y, k0a.y, fmaf(qv.z, k0b.x, qv.w * k0b.y)));
        float d1 = fmaf(qv.x, k1a.x, fmaf(qv.y, k1a.y, fmaf(qv.z, k1b.x, qv.w * k1b.y)));
        d0 += __shfl_xor_sync(0xffffffffu, d0, 1);
        d1 += __shfl_xor_sync(0xffffffffu, d1, 1);
        d0 += __shfl_xor_sync(0xffffffffu, d0, 2);
        d1 += __shfl_xor_sync(0xffffffffu, d1, 2);
        const float w0 = __expf(d0 * 0.25f);
        const float w1 = __expf(d1 * 0.25f);
        ssum += w0 + w1;

        float2 va = __half22float2(*(const __half2*)&v0.x);
        float2 vb = __half22float2(*(const __half2*)&v0.y);
        alp.x = fmaf(w0, va.x, alp.x); alp.y = fmaf(w0, va.y, alp.y);
        alp.z = fmaf(w0, vb.x, alp.z); alp.w = fmaf(w0, vb.y, alp.w);
        va = __half22float2(*(const __half2*)&v1.x);
        vb = __half22float2(*(const __half2*)&v1.y);
        alp.x = fmaf(w1, va.x, alp.x); alp.y = fmaf(w1, va.y, alp.y);
        alp.z = fmaf(w1, vb.x, alp.z); alp.w = fmaf(w1, vb.y, alp.w);

        float2 pa = __half22float2(*(const __half2*)&p0.x);
        float2 pb = __half22float2(*(const __half2*)&p0.y);
        abp.x = fmaf(w0, pa.x, abp.x); abp.y = fmaf(w0, pa.y, abp.y);
        abp.z = fmaf(w0, pb.x, abp.z); abp.w = fmaf(w0, pb.y, abp.w);
        pa = __half22float2(*(const __half2*)&p1.x);
        pb = __half22float2(*(const __half2*)&p1.y);
        abp.x = fmaf(w1, pa.x, abp.x); abp.y = fmaf(w1, pa.y, abp.y);
        abp.z = fmaf(w1, pb.x, abp.z); abp.w = fmaf(w1, pb.y, abp.w);
    }
    if (e < s1) {
        const int c0 = g_scol[e];
        const uint2* b0 = kvp + c0 * 96 + lane;
        const uint2 k0 = b0[0];
        const uint2 v0 = b0[32];
        const uint2 p0 = b0[64];
        float2 k0a = __half22float2(*(const __half2*)&k0.x);
        float2 k0b = __half22float2(*(const __half2*)&k0.y);
        float d0 = fmaf(qv.x, k0a.x, fmaf(qv.y, k0a.y, fmaf(qv.z, k0b.x, qv.w * k0b.y)));
        d0 += __shfl_xor_sync(0xffffffffu, d0, 1);
        d0 += __shfl_xor_sync(0xffffffffu, d0, 2);
        const float w0 = __expf(d0 * 0.25f);
        ssum += w0;
        float2 va = __half22float2(*(const __half2*)&v0.x);
        float2 vb = __half22float2(*(const __half2*)&v0.y);
        alp.x = fmaf(w0, va.x, alp.x); alp.y = fmaf(w0, va.y, alp.y);
        alp.z = fmaf(w0, vb.x, alp.z); alp.w = fmaf(w0, vb.y, alp.w);
        float2 pa = __half22float2(*(const __half2*)&p0.x);
        float2 pb = __half22float2(*(const __half2*)&p0.y);
        abp.x = fmaf(w0, pa.x, abp.x); abp.y = fmaf(w0, pa.y, abp.y);
        abp.z = fmaf(w0, pb.x, abp.z); abp.w = fmaf(w0, pb.y, abp.w);
    }
    const float inv = 1.f / (ssum + 1e-16f);
    float4 o;
    o.x = alp.x * inv; o.y = alp.y * inv; o.z = alp.z * inv; o.w = alp.w * inv;
    *((float4*)(g_hcat + (size_t)r * 256) + lane) = o;
    o.x = abp.x * inv; o.y = abp.y * inv; o.z = abp.z * inv; o.w = abp.w * inv;
    *((float4*)(g_hcat + (size_t)r * 256 + 128) + lane) = o;
}

// ---------------- output GEMM + residual + ReLU + LayerNorm ----------------
// Block: 64 rows x 128 cols, 256 threads, 4x8 per thread; H tile transposed
// in smem. Row moments reduced with shfl over the 16 lanes sharing a row.
__global__ void __launch_bounds__(256) final_kernel(const float* __restrict__ X,
                                                    const float* __restrict__ Wo,
                                                    const float* __restrict__ bo,
                                                    const float* __restrict__ gamma,
                                                    const float* __restrict__ beta,
                                                    float* __restrict__ Y) {
    extern __shared__ float sm[];
    float* Ws = sm;               // [256 k][128 col]
    float* Hs = sm + 256 * 128;   // [256 k][68] transposed H tile (rows 0..63)

    const int t = threadIdx.x;
    const int r0 = blockIdx.x * 64;

    for (int i = t; i < 256 * 32; i += 256)
        ((float4*)Ws)[i] = ((const float4*)Wo)[i];
    for (int i = t; i < 64 * 64; i += 256) {
        int row = i >> 6, c4 = i & 63;
        int gr = r0 + row;
        float4 val = make_float4(0.f, 0.f, 0.f, 0.f);
        if (gr < NN) val = ((const float4*)(g_hcat + (size_t)gr * 256))[c4];
        Hs[(4 * c4 + 0) * 68 + row] = val.x;
        Hs[(4 * c4 + 1) * 68 + row] = val.y;
        Hs[(4 * c4 + 2) * 68 + row] = val.z;
        Hs[(4 * c4 + 3) * 68 + row] = val.w;
    }
    __syncthreads();

    const int tx = t & 15;
    const int ty = t >> 4;

    float acc[4][8];
    {
        float4 c0 = *((const float4*)(bo + tx * 4));
        float4 c1 = *((const float4*)(bo + 64 + tx * 4));
#pragma unroll
        for (int i = 0; i < 4; i++) {
            acc[i][0] = c0.x; acc[i][1] = c0.y; acc[i][2] = c0.z; acc[i][3] = c0.w;
            acc[i][4] = c1.x; acc[i][5] = c1.y; acc[i][6] = c1.z; acc[i][7] = c1.w;
        }
    }

#pragma unroll 4
    for (int k = 0; k < 256; k++) {
        float4 a  = *((const float4*)(Hs + k * 68 + ty * 4));
        float4 b0 = *((const float4*)(Ws + k * 128 + tx * 4));
        float4 b1 = *((const float4*)(Ws + k * 128 + 64 + tx * 4));
        float av[4] = {a.x, a.y, a.z, a.w};
        float bw[8] = {b0.x, b0.y, b0.z, b0.w, b1.x, b1.y, b1.z, b1.w};
#pragma unroll
        for (int i = 0; i < 4; i++)
#pragma unroll
            for (int j = 0; j < 8; j++)
                acc[i][j] = fmaf(av[i], bw[j], acc[i][j]);
    }

    const float4 gm0 = *((const float4*)(gamma + tx * 4));
    const float4 gm1 = *((const float4*)(gamma + 64 + tx * 4));
    const float4 bt0 = *((const float4*)(beta + tx * 4));
    const float4 bt1 = *((const float4*)(beta + 64 + tx * 4));

#pragma unroll
    for (int i = 0; i < 4; i++) {
        int gr = r0 + ty * 4 + i;
        bool ok = gr < NN;
        float4 x0 = make_float4(0.f, 0.f, 0.f, 0.f);
        float4 x1 = make_float4(0.f, 0.f, 0.f, 0.f);
        if (ok) {
            x0 = *((const float4*)(X + (size_t)gr * 128 + tx * 4));
            x1 = *((const float4*)(X + (size_t)gr * 128 + 64 + tx * 4));
        }
        float y[8];
        y[0] = x0.x + fmaxf(acc[i][0], 0.f);
        y[1] = x0.y + fmaxf(acc[i][1], 0.f);
        y[2] = x0.z + fmaxf(acc[i][2], 0.f);
        y[3] = x0.w + fmaxf(acc[i][3], 0.f);
        y[4] = x1.x + fmaxf(acc[i][4], 0.f);
        y[5] = x1.y + fmaxf(acc[i][5], 0.f);
        y[6] = x1.z + fmaxf(acc[i][6], 0.f);
        y[7] = x1.w + fmaxf(acc[i][7], 0.f);
        float ps = 0.f, pq = 0.f;
#pragma unroll
        for (int j = 0; j < 8; j++) { ps += y[j]; pq += y[j] * y[j]; }
        // reduce across the 16 lanes (same ty) that own this row
#pragma unroll
        for (int off = 1; off < 16; off <<= 1) {
            ps += __shfl_xor_sync(0xffffffffu, ps, off);
            pq += __shfl_xor_sync(0xffffffffu, pq, off);
        }
        float mu = ps * (1.f / 128.f);
        float sq = pq * (1.f / 128.f);
        float rsig = rsqrtf(sq - mu * mu + 1e-5f);
        if (ok) {
            float4 o;
            o.x = (y[0] - mu) * rsig * gm0.x + bt0.x;
            o.y = (y[1] - mu) * rsig * gm0.y + bt0.y;
            o.z = (y[2] - mu) * rsig * gm0.z + bt0.z;
            o.w = (y[3] - mu) * rsig * gm0.w + bt0.w;
            *((float4*)(Y + (size_t)gr * 128 + tx * 4)) = o;
            o.x = (y[4] - mu) * rsig * gm1.x + bt1.x;
            o.y = (y[5] - mu) * rsig * gm1.y + bt1.y;
            o.z = (y[6] - mu) * rsig * gm1.z + bt1.z;
            o.w = (y[7] - mu) * rsig * gm1.w + bt1.w;
            *((float4*)(Y + (size_t)gr * 128 + 64 + tx * 4)) = o;
        }
    }
}

// ---------------- launch ----------------
extern "C" void kernel_launch(void* const* d_in, const int* in_sizes, int n_in,
                              void* d_out, int out_size) {
    const float* x     = (const float*)d_in[0];
    const void*  ei    = d_in[1];
    const float* Wq    = (const float*)d_in[2];
    const float* bq    = (const float*)d_in[3];
    const float* Wk    = (const float*)d_in[4];
    const float* bk    = (const float*)d_in[5];
    const float* Wv    = (const float*)d_in[6];
    const float* bv    = (const float*)d_in[7];
    const float* Wpsi  = (const float*)d_in[8];
    const float* bpsi  = (const float*)d_in[9];
    const float* Wo    = (const float*)d_in[10];
    const float* bo    = (const float*)d_in[11];
    const float* gamma = (const float*)d_in[12];
    const float* beta  = (const float*)d_in[13];
    float* out = (float*)d_out;
    (void)in_sizes; (void)n_in; (void)out_size;

    const int SMEM_QKV   = (128 * 68 + 128 * 128) * 4;   // 100352 B
    const int SMEM_FINAL = (256 * 128 + 256 * 68) * 4;   // 200704 B
    (void)cudaFuncSetAttribute(gemm_qkv,   cudaFuncAttributeMaxDynamicSharedMemorySize, SMEM_QKV);
    (void)cudaFuncSetAttribute(final_kernel, cudaFuncAttributeMaxDynamicSharedMemorySize, SMEM_FINAL);

    // edge preprocessing (counting sort by destination row)
    detect_kernel<<<1, 32>>>((const int*)ei);
    zero_kernel<<<(NN + 1023) / 1024, 1024>>>();
    decode_hist_kernel<<<EE / 1024, 1024>>>(ei);
    scan_kernel<<<1, 1024>>>();
    scatter_kernel<<<EE / 1024, 1024>>>();

    // node-level projections (fused QKV via grid.y)
    gemm_qkv<<<dim3(313, 3), 256, SMEM_QKV>>>(x, Wq, bq, Wk, bk, Wv, bv);
    vpsi_kernel<<<NN / 2, 256>>>(Wpsi, bpsi);

    // fused attention edge pass
    edge_kernel<<<NN / 8, 256>>>();

    // output projection + residual + ReLU + LayerNorm
    final_kernel<<<313, 256, SMEM_FINAL>>>(x, Wo, bo, gamma, beta, out);
}

// round 9
// speedup vs baseline: 1.7988x; 1.0584x over previous
#include <cuda_runtime.h>
#include <cuda_fp16.h>
#include <math.h>

#define NN 20000
#define EE 640000

// ---------------- scratch (static device globals; no allocation) ----------------
__device__ float  g_q[NN * 128];
__device__ __half g_kvp[NN * 384];        // packed per-node record: k[128] | v[128] | psi[128]
__device__ float  g_hcat[NN * 256];
__device__ int    g_row[EE];
__device__ int    g_col[EE];
__device__ int    g_scol[EE];
__device__ int    g_counts[NN];
__device__ int    g_off[NN + 1];
__device__ int    g_cur[NN];
__device__ int    g_is64;

// ---------------- fused: zero counts + edge_index dtype detection ----------------
// 20 blocks x 1024 zero g_counts; block 0 / warp 0 also does the int64 ballot.
__global__ void detect_zero_kernel(const int* __restrict__ p) {
    int i = blockIdx.x * 1024 + threadIdx.x;
    if (i < NN) g_counts[i] = 0;
    if (blockIdx.x == 0 && threadIdx.x < 32) {
        int l = threadIdx.x;
        int bad = (p[2 * l + 1] != 0);
        unsigned m = __ballot_sync(0xffffffffu, bad);
        if (l == 0) g_is64 = (m == 0u) ? 1 : 0;
    }
}

// ---------------- fused decode + histogram ----------------
__global__ void decode_hist_kernel(const void* __restrict__ ei) {
    int e = blockIdx.x * 1024 + threadIdx.x;
    int r, c;
    if (g_is64) {
        const long long* q = (const long long*)ei;
        r = (int)q[e]; c = (int)q[EE + e];
    } else {
        const int* q = (const int*)ei;
        r = q[e]; c = q[EE + e];
    }
    g_row[e] = r;
    g_col[e] = c;
    atomicAdd(&g_counts[r], 1);
}

// ---------------- exclusive scan: chunked warp-shfl, coalesced ----------------
__global__ void scan_kernel() {
    __shared__ int wsums[32];
    const int t = threadIdx.x;
    const int lane = t & 31;
    const int wid = t >> 5;
    int carry = 0;
#pragma unroll
    for (int ch = 0; ch < 20; ch++) {
        int idx = ch * 1024 + t;
        int v = (idx < NN) ? g_counts[idx] : 0;
        // inclusive warp scan
        int s = v;
#pragma unroll
        for (int off = 1; off < 32; off <<= 1) {
            int u = __shfl_up_sync(0xffffffffu, s, off);
            if (lane >= off) s += u;
        }
        if (lane == 31) wsums[wid] = s;
        __syncthreads();
        if (wid == 0) {
            int ws = wsums[lane];
#pragma unroll
            for (int off = 1; off < 32; off <<= 1) {
                int u = __shfl_up_sync(0xffffffffu, ws, off);
                if (lane >= off) ws += u;
            }
            wsums[lane] = ws;
        }
        __syncthreads();
        int blockoff = (wid > 0) ? wsums[wid - 1] : 0;
        int excl = s + blockoff + carry - v;
        if (idx < NN) {
            g_off[idx] = excl;
            g_cur[idx] = excl;
        }
        int total = wsums[31];
        __syncthreads();          // protect wsums before next chunk
        carry += total;
    }
    if (t == 0) g_off[NN] = carry;
}

__global__ void scatter_kernel() {
    int e = blockIdx.x * 1024 + threadIdx.x;
    int r = g_row[e];
    int p = atomicAdd(&g_cur[r], 1);
    g_scol[p] = g_col[e];
}

// ---------------- fused QKV GEMM (+ psi MLP on the v path) ----------------
// Block: 64 rows x 128 cols, 256 threads, each thread 4 rows x 8 cols.
// X tile stored k-major (transposed) so a-frag is one LDS.128 (broadcast).
// grid.y: 0 -> g_q fp32, 1 -> k halves into kvp[+0],
//         2 -> v halves into kvp[+128] AND psi=tanh(v@Wpsi+bpsi) into kvp[+256]
//              (v tile staged to smem for the per-head transpose; same fp32
//               accumulators feed psi, so numerics match the split version).
__global__ void __launch_bounds__(256) gemm_qkv(const float* __restrict__ X,
                                                const float* __restrict__ Wq, const float* __restrict__ bq,
                                                const float* __restrict__ Wk, const float* __restrict__ bk,
                                                const float* __restrict__ Wv, const float* __restrict__ bv,
                                                const float* __restrict__ Wpsi, const float* __restrict__ bpsi) {
    extern __shared__ float sm[];
    float* Xs = sm;              // [128 k][68] transposed X tile (rows 0..63)
    float* Ws = sm + 128 * 68;   // [128 k][128 col]
    float* Wp  = sm + 128 * 68 + 128 * 128;   // 256 floats (Wpsi)
    float* bps = Wp + 256;                    // 16 floats (bpsi)

    const int t = threadIdx.x;
    const int r0 = blockIdx.x * 64;
    const int which = blockIdx.y;
    const float* W = (which == 0) ? Wq : (which == 1) ? Wk : Wv;
    const float* B = (which == 0) ? bq : (which == 1) ? bk : bv;

    Wp[t] = Wpsi[t];                 // 256 threads = 256 elems
    if (t < 16) bps[t] = bpsi[t];

    for (int i = t; i < 64 * 32; i += 256) {
        int row = i >> 5, c4 = i & 31;
        int gr = r0 + row;
        float4 val = make_float4(0.f, 0.f, 0.f, 0.f);
        if (gr < NN) val = ((const float4*)(X + (size_t)gr * 128))[c4];
        Xs[(4 * c4 + 0) * 68 + row] = val.x;
        Xs[(4 * c4 + 1) * 68 + row] = val.y;
        Xs[(4 * c4 + 2) * 68 + row] = val.z;
        Xs[(4 * c4 + 3) * 68 + row] = val.w;
    }
    for (int i = t; i < 128 * 32; i += 256)
        ((float4*)Ws)[i] = ((const float4*)W)[i];
    __syncthreads();

    const int tx = t & 15;       // col group: cols tx*4..+3 and 64+tx*4..+3
    const int ty = t >> 4;       // row group: rows ty*4..+3

    float acc[4][8];
    {
        float4 c0 = *((const float4*)(B + tx * 4));
        float4 c1 = *((const float4*)(B + 64 + tx * 4));
#pragma unroll
        for (int i = 0; i < 4; i++) {
            acc[i][0] = c0.x; acc[i][1] = c0.y; acc[i][2] = c0.z; acc[i][3] = c0.w;
            acc[i][4] = c1.x; acc[i][5] = c1.y; acc[i][6] = c1.z; acc[i][7] = c1.w;
        }
    }

#pragma unroll 4
    for (int k = 0; k < 128; k++) {
        float4 a  = *((const float4*)(Xs + k * 68 + ty * 4));
        float4 b0 = *((const float4*)(Ws + k * 128 + tx * 4));
        float4 b1 = *((const float4*)(Ws + k * 128 + 64 + tx * 4));
        float av[4] = {a.x, a.y, a.z, a.w};
        float bw[8] = {b0.x, b0.y, b0.z, b0.w, b1.x, b1.y, b1.z, b1.w};
#pragma unroll
        for (int i = 0; i < 4; i++)
#pragma unroll
            for (int j = 0; j < 8; j++)
                acc[i][j] = fmaf(av[i], bw[j], acc[i][j]);
    }

#pragma unroll
    for (int i = 0; i < 4; i++) {
        int gr = r0 + ty * 4 + i;
        if (gr >= NN) continue;
        if (which == 0) {
            *((float4*)(g_q + (size_t)gr * 128 + tx * 4)) =
                make_float4(acc[i][0], acc[i][1], acc[i][2], acc[i][3]);
            *((float4*)(g_q + (size_t)gr * 128 + 64 + tx * 4)) =
                make_float4(acc[i][4], acc[i][5], acc[i][6], acc[i][7]);
        } else {
            // halves into packed record: k at +0, v at +128
            __half* dst = g_kvp + (size_t)gr * 384 + ((which == 1) ? 0 : 128);
            *((__half2*)(dst + tx * 4))     = __floats2half2_rn(acc[i][0], acc[i][1]);
            *((__half2*)(dst + tx * 4 + 2)) = __floats2half2_rn(acc[i][2], acc[i][3]);
            *((__half2*)(dst + 64 + tx * 4))     = __floats2half2_rn(acc[i][4], acc[i][5]);
            *((__half2*)(dst + 64 + tx * 4 + 2)) = __floats2half2_rn(acc[i][6], acc[i][7]);
        }
    }

    if (which == 2) {
        // stage fp32 v tile into smem (reuse Xs region) for the head transpose
        float* vsm = sm;          // 64 x 132
        __syncthreads();          // everyone done with Xs/Ws
#pragma unroll
        for (int i = 0; i < 4; i++) {
            int row = ty * 4 + i;
            vsm[row * 132 + tx * 4 + 0] = acc[i][0];
            vsm[row * 132 + tx * 4 + 1] = acc[i][1];
            vsm[row * 132 + tx * 4 + 2] = acc[i][2];
            vsm[row * 132 + tx * 4 + 3] = acc[i][3];
            vsm[row * 132 + 64 + tx * 4 + 0] = acc[i][4];
            vsm[row * 132 + 64 + tx * 4 + 1] = acc[i][5];
            vsm[row * 132 + 64 + tx * 4 + 2] = acc[i][6];
            vsm[row * 132 + 64 + tx * 4 + 3] = acc[i][7];
        }
        __syncthreads();
        // psi: thread t handles row = t>>2, cols (t&3)*32 .. +31 (pairs)
        const int row = t >> 2;
        const int grp = t & 3;
        const int gr = r0 + row;
        if (gr < NN) {
            __half* dst = g_kvp + (size_t)gr * 384 + 256;
            const float* vrow = vsm + row * 132;
#pragma unroll
            for (int j = 0; j < 32; j += 2) {
                const int c = grp * 32 + j;          // even -> c, c+1 share a head
                const int head = c >> 4;
                const int d0 = c & 15, d1 = (c + 1) & 15;
                float s0 = bps[d0], s1 = bps[d1];
                const float* vh = vrow + head * 16;
#pragma unroll
                for (int d = 0; d < 16; d++) {
                    s0 = fmaf(vh[d], Wp[d * 16 + d0], s0);
                    s1 = fmaf(vh[d], Wp[d * 16 + d1], s1);
                }
                *((__half2*)(dst + c)) = __floats2half2_rn(tanhf(s0), tanhf(s1));
            }
        }
    }
}

// ---------------- fused edge pass: one warp per destination row ----------------
// Packed half record per source node: k|v|psi (768B). Per edge the warp loads
// 3x256B. fp32 math: dot via 4-lane butterfly, exp weight, fp32 accumulators,
// one normalization at the end (softmax denominator folds out of the max pass).
__global__ void __launch_bounds__(256) edge_kernel() {
    const int r = (blockIdx.x << 3) + (threadIdx.x >> 5);
    const int lane = threadIdx.x & 31;
    const int s0 = g_off[r];
    const int s1 = g_off[r + 1];
    const float4 qv = *((const float4*)(g_q + (size_t)r * 128) + lane);
    float4 alp = make_float4(0.f, 0.f, 0.f, 0.f);
    float4 abp = make_float4(0.f, 0.f, 0.f, 0.f);
    float ssum = 0.f;
    const uint2* kvp = (const uint2*)g_kvp;   // 96 uint2 (=384 halves) per node

    int e = s0;
    for (; e + 2 <= s1; e += 2) {
        const int c0 = g_scol[e];
        const int c1 = g_scol[e + 1];
        const uint2* b0 = kvp + c0 * 96 + lane;
        const uint2* b1 = kvp + c1 * 96 + lane;
        const uint2 k0 = b0[0],  k1 = b1[0];
        const uint2 v0 = b0[32], v1 = b1[32];
        const uint2 p0 = b0[64], p1 = b1[64];

        float2 k0a = __half22float2(*(const __half2*)&k0.x);
        float2 k0b = __half22float2(*(const __half2*)&k0.y);
        float2 k1a = __half22float2(*(const __half2*)&k1.x);
        float2 k1b = __half22float2(*(const __half2*)&k1.y);
        float d0 = fmaf(qv.x, k0a.x, fmaf(qv.y, k0a.y, fmaf(qv.z, k0b.x, qv.w * k0b.y)));
        float d1 = fmaf(qv.x, k1a.x, fmaf(qv.y, k1a.y, fmaf(qv.z, k1b.x, qv.w * k1b.y)));
        d0 += __shfl_xor_sync(0xffffffffu, d0, 1);
        d1 += __shfl_xor_sync(0xffffffffu, d1, 1);
        d0 += __shfl_xor_sync(0xffffffffu, d0, 2);
        d1 += __shfl_xor_sync(0xffffffffu, d1, 2);
        const float w0 = __expf(d0 * 0.25f);
        const float w1 = __expf(d1 * 0.25f);
        ssum += w0 + w1;

        float2 va = __half22float2(*(const __half2*)&v0.x);
        float2 vb = __half22float2(*(const __half2*)&v0.y);
        alp.x = fmaf(w0, va.x, alp.x); alp.y = fmaf(w0, va.y, alp.y);
        alp.z = fmaf(w0, vb.x, alp.z); alp.w = fmaf(w0, vb.y, alp.w);
        va = __half22float2(*(const __half2*)&v1.x);
        vb = __half22float2(*(const __half2*)&v1.y);
        alp.x = fmaf(w1, va.x, alp.x); alp.y = fmaf(w1, va.y, alp.y);
        alp.z = fmaf(w1, vb.x, alp.z); alp.w = fmaf(w1, vb.y, alp.w);

        float2 pa = __half22float2(*(const __half2*)&p0.x);
        float2 pb = __half22float2(*(const __half2*)&p0.y);
        abp.x = fmaf(w0, pa.x, abp.x); abp.y = fmaf(w0, pa.y, abp.y);
        abp.z = fmaf(w0, pb.x, abp.z); abp.w = fmaf(w0, pb.y, abp.w);
        pa = __half22float2(*(const __half2*)&p1.x);
        pb = __half22float2(*(const __half2*)&p1.y);
        abp.x = fmaf(w1, pa.x, abp.x); abp.y = fmaf(w1, pa.y, abp.y);
        abp.z = fmaf(w1, pb.x, abp.z); abp.w = fmaf(w1, pb.y, abp.w);
    }
    if (e < s1) {
        const int c0 = g_scol[e];
        const uint2* b0 = kvp + c0 * 96 + lane;
        const uint2 k0 = b0[0];
        const uint2 v0 = b0[32];
        const uint2 p0 = b0[64];
        float2 k0a = __half22float2(*(const __half2*)&k0.x);
        float2 k0b = __half22float2(*(const __half2*)&k0.y);
        float d0 = fmaf(qv.x, k0a.x, fmaf(qv.y, k0a.y, fmaf(qv.z, k0b.x, qv.w * k0b.y)));
        d0 += __shfl_xor_sync(0xffffffffu, d0, 1);
        d0 += __shfl_xor_sync(0xffffffffu, d0, 2);
        const float w0 = __expf(d0 * 0.25f);
        ssum += w0;
        float2 va = __half22float2(*(const __half2*)&v0.x);
        float2 vb = __half22float2(*(const __half2*)&v0.y);
        alp.x = fmaf(w0, va.x, alp.x); alp.y = fmaf(w0, va.y, alp.y);
        alp.z = fmaf(w0, vb.x, alp.z); alp.w = fmaf(w0, vb.y, alp.w);
        float2 pa = __half22float2(*(const __half2*)&p0.x);
        float2 pb = __half22float2(*(const __half2*)&p0.y);
        abp.x = fmaf(w0, pa.x, abp.x); abp.y = fmaf(w0, pa.y, abp.y);
        abp.z = fmaf(w0, pb.x, abp.z); abp.w = fmaf(w0, pb.y, abp.w);
    }
    const float inv = 1.f / (ssum + 1e-16f);
    float4 o;
    o.x = alp.x * inv; o.y = alp.y * inv; o.z = alp.z * inv; o.w = alp.w * inv;
    *((float4*)(g_hcat + (size_t)r * 256) + lane) = o;
    o.x = abp.x * inv; o.y = abp.y * inv; o.z = abp.z * inv; o.w = abp.w * inv;
    *((float4*)(g_hcat + (size_t)r * 256 + 128) + lane) = o;
}

// ---------------- output GEMM + residual + ReLU + LayerNorm ----------------
// Block: 64 rows x 128 cols, 256 threads, 4x8 per thread; H tile transposed
// in smem. Row moments reduced with shfl over the 16 lanes sharing a row.
__global__ void __launch_bounds__(256) final_kernel(const float* __restrict__ X,
                                                    const float* __restrict__ Wo,
                                                    const float* __restrict__ bo,
                                                    const float* __restrict__ gamma,
                                                    const float* __restrict__ beta,
                                                    float* __restrict__ Y) {
    extern __shared__ float sm[];
    float* Ws = sm;               // [256 k][128 col]
    float* Hs = sm + 256 * 128;   // [256 k][68] transposed H tile (rows 0..63)

    const int t = threadIdx.x;
    const int r0 = blockIdx.x * 64;

    for (int i = t; i < 256 * 32; i += 256)
        ((float4*)Ws)[i] = ((const float4*)Wo)[i];
    for (int i = t; i < 64 * 64; i += 256) {
        int row = i >> 6, c4 = i & 63;
        int gr = r0 + row;
        float4 val = make_float4(0.f, 0.f, 0.f, 0.f);
        if (gr < NN) val = ((const float4*)(g_hcat + (size_t)gr * 256))[c4];
        Hs[(4 * c4 + 0) * 68 + row] = val.x;
        Hs[(4 * c4 + 1) * 68 + row] = val.y;
        Hs[(4 * c4 + 2) * 68 + row] = val.z;
        Hs[(4 * c4 + 3) * 68 + row] = val.w;
    }
    __syncthreads();

    const int tx = t & 15;
    const int ty = t >> 4;

    float acc[4][8];
    {
        float4 c0 = *((const float4*)(bo + tx * 4));
        float4 c1 = *((const float4*)(bo + 64 + tx * 4));
#pragma unroll
        for (int i = 0; i < 4; i++) {
            acc[i][0] = c0.x; acc[i][1] = c0.y; acc[i][2] = c0.z; acc[i][3] = c0.w;
            acc[i][4] = c1.x; acc[i][5] = c1.y; acc[i][6] = c1.z; acc[i][7] = c1.w;
        }
    }

#pragma unroll 4
    for (int k = 0; k < 256; k++) {
        float4 a  = *((const float4*)(Hs + k * 68 + ty * 4));
        float4 b0 = *((const float4*)(Ws + k * 128 + tx * 4));
        float4 b1 = *((const float4*)(Ws + k * 128 + 64 + tx * 4));
        float av[4] = {a.x, a.y, a.z, a.w};
        float bw[8] = {b0.x, b0.y, b0.z, b0.w, b1.x, b1.y, b1.z, b1.w};
#pragma unroll
        for (int i = 0; i < 4; i++)
#pragma unroll
            for (int j = 0; j < 8; j++)
                acc[i][j] = fmaf(av[i], bw[j], acc[i][j]);
    }

    const float4 gm0 = *((const float4*)(gamma + tx * 4));
    const float4 gm1 = *((const float4*)(gamma + 64 + tx * 4));
    const float4 bt0 = *((const float4*)(beta + tx * 4));
    const float4 bt1 = *((const float4*)(beta + 64 + tx * 4));

#pragma unroll
    for (int i = 0; i < 4; i++) {
        int gr = r0 + ty * 4 + i;
        bool ok = gr < NN;
        float4 x0 = make_float4(0.f, 0.f, 0.f, 0.f);
        float4 x1 = make_float4(0.f, 0.f, 0.f, 0.f);
        if (ok) {
            x0 = *((const float4*)(X + (size_t)gr * 128 + tx * 4));
            x1 = *((const float4*)(X + (size_t)gr * 128 + 64 + tx * 4));
        }
        float y[8];
        y[0] = x0.x + fmaxf(acc[i][0], 0.f);
        y[1] = x0.y + fmaxf(acc[i][1], 0.f);
        y[2] = x0.z + fmaxf(acc[i][2], 0.f);
        y[3] = x0.w + fmaxf(acc[i][3], 0.f);
        y[4] = x1.x + fmaxf(acc[i][4], 0.f);
        y[5] = x1.y + fmaxf(acc[i][5], 0.f);
        y[6] = x1.z + fmaxf(acc[i][6], 0.f);
        y[7] = x1.w + fmaxf(acc[i][7], 0.f);
        float ps = 0.f, pq = 0.f;
#pragma unroll
        for (int j = 0; j < 8; j++) { ps += y[j]; pq += y[j] * y[j]; }
        // reduce across the 16 lanes (same ty) that own this row
#pragma unroll
        for (int off = 1; off < 16; off <<= 1) {
            ps += __shfl_xor_sync(0xffffffffu, ps, off);
            pq += __shfl_xor_sync(0xffffffffu, pq, off);
        }
        float mu = ps * (1.f / 128.f);
        float sq = pq * (1.f / 128.f);
        float rsig = rsqrtf(sq - mu * mu + 1e-5f);
        if (ok) {
            float4 o;
            o.x = (y[0] - mu) * rsig * gm0.x + bt0.x;
            o.y = (y[1] - mu) * rsig * gm0.y + bt0.y;
            o.z = (y[2] - mu) * rsig * gm0.z + bt0.z;
            o.w = (y[3] - mu) * rsig * gm0.w + bt0.w;
            *((float4*)(Y + (size_t)gr * 128 + tx * 4)) = o;
            o.x = (y[4] - mu) * rsig * gm1.x + bt1.x;
            o.y = (y[5] - mu) * rsig * gm1.y + bt1.y;
            o.z = (y[6] - mu) * rsig * gm1.z + bt1.z;
            o.w = (y[7] - mu) * rsig * gm1.w + bt1.w;
            *((float4*)(Y + (size_t)gr * 128 + 64 + tx * 4)) = o;
        }
    }
}

// ---------------- launch ----------------
extern "C" void kernel_launch(void* const* d_in, const int* in_sizes, int n_in,
                              void* d_out, int out_size) {
    const float* x     = (const float*)d_in[0];
    const void*  ei    = d_in[1];
    const float* Wq    = (const float*)d_in[2];
    const float* bq    = (const float*)d_in[3];
    const float* Wk    = (const float*)d_in[4];
    const float* bk    = (const float*)d_in[5];
    const float* Wv    = (const float*)d_in[6];
    const float* bv    = (const float*)d_in[7];
    const float* Wpsi  = (const float*)d_in[8];
    const float* bpsi  = (const float*)d_in[9];
    const float* Wo    = (const float*)d_in[10];
    const float* bo    = (const float*)d_in[11];
    const float* gamma = (const float*)d_in[12];
    const float* beta  = (const float*)d_in[13];
    float* out = (float*)d_out;
    (void)in_sizes; (void)n_in; (void)out_size;

    const int SMEM_QKV   = (128 * 68 + 128 * 128 + 256 + 16) * 4;  // 101440 B
    const int SMEM_FINAL = (256 * 128 + 256 * 68) * 4;             // 200704 B
    (void)cudaFuncSetAttribute(gemm_qkv,     cudaFuncAttributeMaxDynamicSharedMemorySize, SMEM_QKV);
    (void)cudaFuncSetAttribute(final_kernel, cudaFuncAttributeMaxDynamicSharedMemorySize, SMEM_FINAL);

    // edge preprocessing (counting sort by destination row)
    detect_zero_kernel<<<20, 1024>>>((const int*)ei);
    decode_hist_kernel<<<EE / 1024, 1024>>>(ei);
    scan_kernel<<<1, 1024>>>();
    scatter_kernel<<<EE / 1024, 1024>>>();

    // node-level projections (fused QKV + psi via grid.y)
    gemm_qkv<<<dim3(313, 3), 256, SMEM_QKV>>>(x, Wq, bq, Wk, bk, Wv, bv, Wpsi, bpsi);

    // fused attention edge pass
    edge_kernel<<<NN / 8, 256>>>();

    // output projection + residual + ReLU + LayerNorm
    final_kernel<<<313, 256, SMEM_FINAL>>>(x, Wo, bo, gamma, beta, out);
}